// round 13
// baseline (speedup 1.0000x reference)
#include <cuda_runtime.h>
#include <cuda_fp16.h>
#include <cstdint>
#include <cfloat>

// ---------------- problem constants ----------------
#define M_TOT 4096          // B*N*H*W
#define C_TOT 256           // K
#define NPAGE 256           // B*N pages (each 16 m's x 256 c's)
#define NCHUNK 4            // K chunks of 64
#define NPART 32            // partials per row = 4096/128
#define NFBLK 16            // finalize blocks
#define L2E   1.4426950408889634f
#define SOFF  20.0f         // fixed softmax offset: lse = SOFF + log(sum)

// ---------------- scratch ----------------
__device__ __align__(16) __half g_p16[M_TOT * C_TOT];
__device__ __align__(16) __half g_g16[M_TOT * C_TOT];
__device__ float g_diag[M_TOT];
// transposed partials: [tile][row] -> coalesced write and read
__device__ float g_pmax[NPART * M_TOT];
__device__ float g_psum[NPART * M_TOT];   // sum of exp(x - SOFF), raw
__device__ int   g_pami[NPART * M_TOT];
__device__ float g_blk_loss[NFBLK];
__device__ int   g_blk_corr[NFBLK];
__device__ unsigned g_done = 0;    // arrival counter (reset by last block)

// ---------------- helpers ----------------
__device__ __forceinline__ uint32_t smem_u32(const void* p) {
    uint32_t a;
    asm("{ .reg .u64 t; cvta.to.shared.u64 t, %1; cvt.u32.u64 %0, t; }"
        : "=r"(a) : "l"(p));
    return a;
}
#define SWZ128(o) ((o) ^ (((o) >> 3) & 0x70))

__device__ __forceinline__ void ldsm4(uint32_t* r, uint32_t addr) {
    asm volatile("ldmatrix.sync.aligned.m8n8.x4.shared.b16 {%0,%1,%2,%3}, [%4];"
                 : "=r"(r[0]), "=r"(r[1]), "=r"(r[2]), "=r"(r[3]) : "r"(addr));
}
__device__ __forceinline__ void mma_fp16(float* d, const uint32_t* a,
                                         const uint32_t* b) {
    asm volatile(
        "mma.sync.aligned.m16n8k16.row.col.f32.f16.f16.f32 "
        "{%0,%1,%2,%3}, {%4,%5,%6,%7}, {%8,%9}, {%0,%1,%2,%3};"
        : "+f"(d[0]), "+f"(d[1]), "+f"(d[2]), "+f"(d[3])
        : "r"(a[0]), "r"(a[1]), "r"(a[2]), "r"(a[3]), "r"(b[0]), "r"(b[1]));
}
__device__ __forceinline__ float ex2(float x) {
    float r;
    asm("ex2.approx.ftz.f32 %0, %1;" : "=f"(r) : "f"(x));
    return r;
}
__device__ __forceinline__ void cp16(uint32_t smem_addr, const void* gptr) {
    asm volatile("cp.async.ca.shared.global [%0], [%1], 16;"
                 :: "r"(smem_addr), "l"(__cvta_generic_to_global(gptr)));
}
#define CP_COMMIT() asm volatile("cp.async.commit_group;" ::: "memory")
#define CP_WAIT1()  asm volatile("cp.async.wait_group 1;" ::: "memory")
#define CP_WAIT0()  asm volatile("cp.async.wait_group 0;" ::: "memory")

// smem layout: two 32KB stages (A 16KB + B 16KB) + stats
#define STG_SZ  32768
#define SM_A    0
#define SM_B    16384
#define SM_SMX  65536                 // float [4][128]
#define SM_SSM  (65536 + 2048)        // float [4][128]
#define SM_SAR  (65536 + 4096)        // int   [4][128]
#define SM_TOTAL (65536 + 6144)

// ---------------------------------------------------------------------------
// Kernel 0: pack (B,N,C,H,W) f32 -> row-major [M][C] fp16. (R11 version)
// ---------------------------------------------------------------------------
__global__ void __launch_bounds__(256) pack_kernel(const float* __restrict__ pred,
                                                   const float* __restrict__ gt) {
    __shared__ float s[16 * 130];
    const int tid  = threadIdx.x;
    const int half = blockIdx.x & 1;
    const int page = (blockIdx.x >> 1) & (NPAGE - 1);
    const bool is_p = blockIdx.x < 2 * NPAGE;
    const float4* src4 =
        (const float4*)((is_p ? pred : gt) + (size_t)page * 4096);
    __half2* dst = (__half2*)(is_p ? g_p16 : g_g16);

    #pragma unroll
    for (int i = 0; i < 2; i++) {
        int qq = half * 512 + tid + i * 256;
        int c = qq >> 2, hw0 = (qq & 3) * 4;
        int cl = c - half * 128;
        float4 v = src4[qq];
        s[(hw0 + 0) * 130 + cl] = v.x;
        s[(hw0 + 1) * 130 + cl] = v.y;
        s[(hw0 + 2) * 130 + cl] = v.z;
        s[(hw0 + 3) * 130 + cl] = v.w;
    }
    __syncthreads();
    #pragma unroll
    for (int i = 0; i < 4; i++) {
        int o = tid + i * 256;
        int hw = o >> 6, j = o & 63;
        __half2 v = __floats2half2_rn(s[hw * 130 + j * 2],
                                      s[hw * 130 + j * 2 + 1]);
        dst[(size_t)(page * 16 + hw) * 128 + half * 64 + j] = v;
    }
}

// ---------------------------------------------------------------------------
// Kernel 1: fp16 HMMA GEMM + fused softmax stats (fixed-offset exp).
// CTA 128x128 tile; 8 warps as 2(row) x 4(col); warp tile 64x32; 2 CTAs/SM.
// Swizzle hoisted out of the mainloop (carry-free algebra, see notes).
// ---------------------------------------------------------------------------
__global__ void __launch_bounds__(256, 2) gemm_softmax_kernel() {
    extern __shared__ __align__(1024) char sm[];
    const uint32_t sb = smem_u32(sm);
    const int tid  = threadIdx.x;
    const int wid  = tid >> 5;
    const int lane = tid & 31;
    const int rb = blockIdx.x >> 5;   // 0..31 row block
    const int cb = blockIdx.x & 31;   // 0..31 col block

    const int wr = wid >> 2;          // 0..1 warp row (64 rows)
    const int wc = wid & 3;           // 0..3 warp col (32 cols)

    const uint32_t offA0 =
        (uint32_t)((wr * 64 + (lane & 15)) * 128 + (lane >> 4) * 16);
    const uint32_t offB0 =
        (uint32_t)((wc * 32 + ((lane >> 4) & 1) * 8 + (lane & 7)) * 128 +
                   ((lane >> 3) & 1) * 16);
    // hoisted swizzle: mask depends only on row%8 (lane-constant); kx (bits
    // 5-6) and mt/np*2048 (bit 11+) are carry-free vs offA0/offB0, so
    // SWZ128(off + d + kx) == (off ^ M) + d, with kx XORed into the address.
    const uint32_t swA = offA0 ^ ((offA0 >> 3) & 0x70);
    const uint32_t swB = offB0 ^ ((offB0 >> 3) & 0x70);

    const uint4* srcA = (const uint4*)g_p16;
    const uint4* srcB = (const uint4*)g_g16;

    auto prefetch = [&](int ch, int s) {
        const uint32_t base = sb + s * STG_SZ;
        #pragma unroll
        for (int t = tid; t < 1024; t += 256) {
            int r = t >> 3, sg = t & 7;
            uint32_t sw = SWZ128((uint32_t)(r * 128 + sg * 16));
            int giA = (rb * 128 + r) * 32 + ch * 8 + sg;
            int giB = (cb * 128 + r) * 32 + ch * 8 + sg;
            cp16(base + SM_A + sw, &srcA[giA]);
            cp16(base + SM_B + sw, &srcB[giB]);
        }
        CP_COMMIT();
    };

    float acc[4][4][4];
    #pragma unroll
    for (int a = 0; a < 4; a++)
        #pragma unroll
        for (int b = 0; b < 4; b++)
            #pragma unroll
            for (int c = 0; c < 4; c++) acc[a][b][c] = 0.f;

    prefetch(0, 0);

    for (int ch = 0; ch < NCHUNK; ch++) {
        const uint32_t stage = sb + (ch & 1) * STG_SZ;
        if (ch + 1 < NCHUNK) {
            prefetch(ch + 1, (ch + 1) & 1);
            CP_WAIT1();
        } else {
            CP_WAIT0();
        }
        __syncthreads();

        const uint32_t aBase = stage + SM_A + swA;
        const uint32_t bBase = stage + SM_B + swB;

        #pragma unroll
        for (int ks = 0; ks < 4; ks++) {
            const uint32_t ax = aBase ^ (uint32_t)(ks * 32);
            const uint32_t bx = bBase ^ (uint32_t)(ks * 32);
            uint32_t bf[2][4];
            ldsm4(bf[0], bx);
            ldsm4(bf[1], bx + 2048);
            #pragma unroll
            for (int mt = 0; mt < 4; mt++) {
                uint32_t af[4];
                ldsm4(af, ax + mt * 2048);
                #pragma unroll
                for (int nt = 0; nt < 4; nt++)
                    mma_fp16(acc[mt][nt], af, &bf[nt >> 1][(nt & 1) * 2]);
            }
        }
        __syncthreads();
    }

    // ---- epilogue: fixed-offset softmax stats ----
    const int g  = lane >> 2;
    const int qc = lane & 3;
    const bool diag_tile = (rb == cb);
    float* smax = (float*)(sm + SM_SMX);
    float* ssum = (float*)(sm + SM_SSM);
    int*   sarg = (int*)(sm + SM_SAR);
    const float noff = -SOFF * L2E;

    #pragma unroll
    for (int mt = 0; mt < 4; mt++) {
        #pragma unroll
        for (int rp = 0; rp < 2; rp++) {
            const int lrow = wr * 64 + mt * 16 + rp * 8 + g;
            const int grow = rb * 128 + lrow;

            float m = -FLT_MAX;
            int ai = 0;
            #pragma unroll
            for (int nt = 0; nt < 4; nt++) {
                #pragma unroll
                for (int cp = 0; cp < 2; cp++) {
                    float x = acc[mt][nt][rp * 2 + cp];
                    int col = cb * 128 + wc * 32 + nt * 8 + qc * 2 + cp;
                    if (x > m) { m = x; ai = col; }
                }
            }
            if (diag_tile) {
                #pragma unroll
                for (int nt = 0; nt < 4; nt++)
                    #pragma unroll
                    for (int cp = 0; cp < 2; cp++) {
                        int col = cb * 128 + wc * 32 + nt * 8 + qc * 2 + cp;
                        if (col == grow)
                            g_diag[grow] = acc[mt][nt][rp * 2 + cp];
                    }
            }
            float s = 0.f;
            #pragma unroll
            for (int nt = 0; nt < 4; nt++)
                #pragma unroll
                for (int cp = 0; cp < 2; cp++)
                    s += ex2(fmaf(acc[mt][nt][rp * 2 + cp], L2E, noff));

            // quad butterfly: plain sum + max/argmax (no rescale needed)
            #pragma unroll
            for (int off = 1; off < 4; off <<= 1) {
                float m2 = __shfl_xor_sync(0xffffffffu, m, off);
                float s2 = __shfl_xor_sync(0xffffffffu, s, off);
                int   a2 = __shfl_xor_sync(0xffffffffu, ai, off);
                if (m2 > m || (m2 == m && a2 < ai)) ai = a2;
                m = fmaxf(m, m2);
                s += s2;
            }
            if (qc == 0) {
                smax[wc * 128 + lrow] = m;
                ssum[wc * 128 + lrow] = s;
                sarg[wc * 128 + lrow] = ai;
            }
        }
    }
    __syncthreads();

    // ---- merge 4 warp-cols; coalesced transposed write [cb][row] ----
    if (lane < 16) {
        const int lrow = wid * 16 + lane;
        const int grow = rb * 128 + lrow;
        float M = -FLT_MAX, S = 0.f;
        int AI = 0;
        #pragma unroll
        for (int w = 0; w < 4; w++) {
            float v = smax[w * 128 + lrow];
            if (v > M) { M = v; AI = sarg[w * 128 + lrow]; }  // ascending ties
            S += ssum[w * 128 + lrow];
        }
        int pi = cb * M_TOT + grow;
        g_pmax[pi] = M;
        g_psum[pi] = S;
        g_pami[pi] = AI;
    }
}

// ---------------------------------------------------------------------------
// Kernel 2: finalize. S is a plain sum of partials (shared offset SOFF);
// lse = SOFF + log(S). Argmax via max over partial maxima.
// ---------------------------------------------------------------------------
__global__ void __launch_bounds__(256) finalize_kernel(float* __restrict__ out) {
    __shared__ float s_loss[256];
    __shared__ int   s_corr[256];
    __shared__ int   s_last;
    const int tid = threadIdx.x;
    const int r = blockIdx.x * 256 + tid;

    float S = 0.f, bv = -FLT_MAX;
    int AI = 0;
    #pragma unroll
    for (int t = 0; t < NPART; t++) {
        float v = g_pmax[t * M_TOT + r];
        if (v > bv) { bv = v; AI = g_pami[t * M_TOT + r]; }  // first-idx ties
        S += g_psum[t * M_TOT + r];
    }
    float lse = SOFF + logf(S);

    s_loss[tid] = lse - g_diag[r];
    s_corr[tid] = (AI == r) ? 1 : 0;
    __syncthreads();
    for (int o = 128; o > 0; o >>= 1) {
        if (tid < o) {
            s_loss[tid] += s_loss[tid + o];
            s_corr[tid] += s_corr[tid + o];
        }
        __syncthreads();
    }
    if (tid == 0) {
        g_blk_loss[blockIdx.x] = s_loss[0];
        g_blk_corr[blockIdx.x] = s_corr[0];
        __threadfence();
        unsigned prev = atomicAdd(&g_done, 1u);
        s_last = (prev == NFBLK - 1) ? 1 : 0;
    }
    __syncthreads();

    if (s_last && tid == 0) {
        __threadfence();
        float L = 0.f;
        int Cc = 0;
        #pragma unroll
        for (int i = 0; i < NFBLK; i++) {   // fixed order -> deterministic
            L += g_blk_loss[i];
            Cc += g_blk_corr[i];
        }
        out[0] = L / (float)M_TOT;
        out[1] = 100.f * (float)Cc / (float)M_TOT;
        g_done = 0;                          // reset for graph replay
    }
}

// ---------------------------------------------------------------------------
extern "C" void kernel_launch(void* const* d_in, const int* in_sizes, int n_in,
                              void* d_out, int out_size) {
    const float* pred = (const float*)d_in[0];
    const float* gt   = (const float*)d_in[1];

    cudaFuncSetAttribute(gemm_softmax_kernel,
                         cudaFuncAttributeMaxDynamicSharedMemorySize, SM_TOTAL);

    pack_kernel<<<4 * NPAGE, 256>>>(pred, gt);
    gemm_softmax_kernel<<<1024, 256, SM_TOTAL>>>();
    finalize_kernel<<<NFBLK, 256>>>((float*)d_out);
}

// round 14
// speedup vs baseline: 1.4072x; 1.4072x over previous
#include <cuda_runtime.h>
#include <cuda_fp16.h>
#include <cstdint>
#include <cfloat>

// ---------------- problem constants ----------------
#define M_TOT 4096          // B*N*H*W
#define C_TOT 256           // K
#define NPAGE 256           // B*N pages (each 16 m's x 256 c's)
#define NCHUNK 4            // K chunks of 64
#define NPART 32            // partials per row = 4096/128
#define NFBLK 16            // finalize blocks
#define L2E   1.4426950408889634f
#define SOFF  20.0f         // fixed softmax offset: lse = SOFF + log(sum)

// ---------------- scratch ----------------
__device__ __align__(16) __half g_p16[M_TOT * C_TOT];
__device__ __align__(16) __half g_g16[M_TOT * C_TOT];
__device__ float g_diag[M_TOT];
// transposed partials: [tile][row] -> coalesced write and read
__device__ float g_pmax[NPART * M_TOT];
__device__ float g_psum[NPART * M_TOT];   // sum of exp(x - SOFF), raw
__device__ int   g_pami[NPART * M_TOT];
__device__ float g_blk_loss[NFBLK];
__device__ int   g_blk_corr[NFBLK];
__device__ unsigned g_done = 0;    // arrival counter (reset by last block)

// ---------------- helpers ----------------
__device__ __forceinline__ uint32_t smem_u32(const void* p) {
    uint32_t a;
    asm("{ .reg .u64 t; cvta.to.shared.u64 t, %1; cvt.u32.u64 %0, t; }"
        : "=r"(a) : "l"(p));
    return a;
}
#define SWZ128(o) ((o) ^ (((o) >> 3) & 0x70))

__device__ __forceinline__ void ldsm4(uint32_t* r, uint32_t addr) {
    asm volatile("ldmatrix.sync.aligned.m8n8.x4.shared.b16 {%0,%1,%2,%3}, [%4];"
                 : "=r"(r[0]), "=r"(r[1]), "=r"(r[2]), "=r"(r[3]) : "r"(addr));
}
__device__ __forceinline__ void mma_fp16(float* d, const uint32_t* a,
                                         const uint32_t* b) {
    asm volatile(
        "mma.sync.aligned.m16n8k16.row.col.f32.f16.f16.f32 "
        "{%0,%1,%2,%3}, {%4,%5,%6,%7}, {%8,%9}, {%0,%1,%2,%3};"
        : "+f"(d[0]), "+f"(d[1]), "+f"(d[2]), "+f"(d[3])
        : "r"(a[0]), "r"(a[1]), "r"(a[2]), "r"(a[3]), "r"(b[0]), "r"(b[1]));
}
__device__ __forceinline__ float ex2(float x) {
    float r;
    asm("ex2.approx.ftz.f32 %0, %1;" : "=f"(r) : "f"(x));
    return r;
}
__device__ __forceinline__ void cp16(uint32_t smem_addr, const void* gptr) {
    asm volatile("cp.async.ca.shared.global [%0], [%1], 16;"
                 :: "r"(smem_addr), "l"(__cvta_generic_to_global(gptr)));
}
#define CP_COMMIT() asm volatile("cp.async.commit_group;" ::: "memory")
#define CP_WAIT1()  asm volatile("cp.async.wait_group 1;" ::: "memory")
#define CP_WAIT0()  asm volatile("cp.async.wait_group 0;" ::: "memory")

// smem layout: two 32KB stages (A 16KB + B 16KB) + stats
#define STG_SZ  32768
#define SM_A    0
#define SM_B    16384
#define SM_SMX  65536                 // float [4][128]
#define SM_SSM  (65536 + 2048)        // float [4][128]
#define SM_SAR  (65536 + 4096)        // int   [4][128]
#define SM_TOTAL (65536 + 6144)

// ---------------------------------------------------------------------------
// Kernel 0: pack (B,N,C,H,W) f32 -> row-major [M][C] fp16. (R11 version)
// ---------------------------------------------------------------------------
__global__ void __launch_bounds__(256) pack_kernel(const float* __restrict__ pred,
                                                   const float* __restrict__ gt) {
    __shared__ float s[16 * 130];
    const int tid  = threadIdx.x;
    const int half = blockIdx.x & 1;
    const int page = (blockIdx.x >> 1) & (NPAGE - 1);
    const bool is_p = blockIdx.x < 2 * NPAGE;
    const float4* src4 =
        (const float4*)((is_p ? pred : gt) + (size_t)page * 4096);
    __half2* dst = (__half2*)(is_p ? g_p16 : g_g16);

    #pragma unroll
    for (int i = 0; i < 2; i++) {
        int qq = half * 512 + tid + i * 256;
        int c = qq >> 2, hw0 = (qq & 3) * 4;
        int cl = c - half * 128;
        float4 v = src4[qq];
        s[(hw0 + 0) * 130 + cl] = v.x;
        s[(hw0 + 1) * 130 + cl] = v.y;
        s[(hw0 + 2) * 130 + cl] = v.z;
        s[(hw0 + 3) * 130 + cl] = v.w;
    }
    __syncthreads();
    #pragma unroll
    for (int i = 0; i < 4; i++) {
        int o = tid + i * 256;
        int hw = o >> 6, j = o & 63;
        __half2 v = __floats2half2_rn(s[hw * 130 + j * 2],
                                      s[hw * 130 + j * 2 + 1]);
        dst[(size_t)(page * 16 + hw) * 128 + half * 64 + j] = v;
    }
}

// ---------------------------------------------------------------------------
// Kernel 1: fp16 HMMA GEMM (R11 mainloop, verbatim) + fixed-offset softmax
// epilogue (R13). CTA 128x128; 8 warps 2x4; warp tile 64x32; 2 CTAs/SM.
// ---------------------------------------------------------------------------
__global__ void __launch_bounds__(256, 2) gemm_softmax_kernel() {
    extern __shared__ __align__(1024) char sm[];
    const uint32_t sb = smem_u32(sm);
    const int tid  = threadIdx.x;
    const int wid  = tid >> 5;
    const int lane = tid & 31;
    const int rb = blockIdx.x >> 5;   // 0..31 row block
    const int cb = blockIdx.x & 31;   // 0..31 col block

    const int wr = wid >> 2;          // 0..1 warp row (64 rows)
    const int wc = wid & 3;           // 0..3 warp col (32 cols)

    const uint32_t offA0 =
        (uint32_t)((wr * 64 + (lane & 15)) * 128 + (lane >> 4) * 16);
    const uint32_t offB0 =
        (uint32_t)((wc * 32 + ((lane >> 4) & 1) * 8 + (lane & 7)) * 128 +
                   ((lane >> 3) & 1) * 16);

    const uint4* srcA = (const uint4*)g_p16;
    const uint4* srcB = (const uint4*)g_g16;

    auto prefetch = [&](int ch, int s) {
        const uint32_t base = sb + s * STG_SZ;
        #pragma unroll
        for (int t = tid; t < 1024; t += 256) {
            int r = t >> 3, sg = t & 7;
            uint32_t sw = SWZ128((uint32_t)(r * 128 + sg * 16));
            int giA = (rb * 128 + r) * 32 + ch * 8 + sg;
            int giB = (cb * 128 + r) * 32 + ch * 8 + sg;
            cp16(base + SM_A + sw, &srcA[giA]);
            cp16(base + SM_B + sw, &srcB[giB]);
        }
        CP_COMMIT();
    };

    float acc[4][4][4];
    #pragma unroll
    for (int a = 0; a < 4; a++)
        #pragma unroll
        for (int b = 0; b < 4; b++)
            #pragma unroll
            for (int c = 0; c < 4; c++) acc[a][b][c] = 0.f;

    prefetch(0, 0);

    for (int ch = 0; ch < NCHUNK; ch++) {
        const uint32_t stage = sb + (ch & 1) * STG_SZ;
        if (ch + 1 < NCHUNK) {
            prefetch(ch + 1, (ch + 1) & 1);
            CP_WAIT1();
        } else {
            CP_WAIT0();
        }
        __syncthreads();

        #pragma unroll
        for (int ks = 0; ks < 4; ks++) {
            const uint32_t kx = (uint32_t)(ks * 32);
            uint32_t bf[2][4];
            #pragma unroll
            for (int np = 0; np < 2; np++) {
                uint32_t ob = offB0 + np * 2048 + kx;
                ldsm4(bf[np], stage + SM_B + SWZ128(ob));
            }
            #pragma unroll
            for (int mt = 0; mt < 4; mt++) {
                uint32_t oa = offA0 + mt * 2048 + kx;
                uint32_t af[4];
                ldsm4(af, stage + SM_A + SWZ128(oa));
                #pragma unroll
                for (int nt = 0; nt < 4; nt++)
                    mma_fp16(acc[mt][nt], af, &bf[nt >> 1][(nt & 1) * 2]);
            }
        }
        __syncthreads();
    }

    // ---- epilogue: fixed-offset softmax stats (R13) ----
    const int g  = lane >> 2;
    const int qc = lane & 3;
    const bool diag_tile = (rb == cb);
    float* smax = (float*)(sm + SM_SMX);
    float* ssum = (float*)(sm + SM_SSM);
    int*   sarg = (int*)(sm + SM_SAR);
    const float noff = -SOFF * L2E;

    #pragma unroll
    for (int mt = 0; mt < 4; mt++) {
        #pragma unroll
        for (int rp = 0; rp < 2; rp++) {
            const int lrow = wr * 64 + mt * 16 + rp * 8 + g;
            const int grow = rb * 128 + lrow;

            float m = -FLT_MAX;
            int ai = 0;
            #pragma unroll
            for (int nt = 0; nt < 4; nt++) {
                #pragma unroll
                for (int cp = 0; cp < 2; cp++) {
                    float x = acc[mt][nt][rp * 2 + cp];
                    int col = cb * 128 + wc * 32 + nt * 8 + qc * 2 + cp;
                    if (x > m) { m = x; ai = col; }
                }
            }
            if (diag_tile) {
                #pragma unroll
                for (int nt = 0; nt < 4; nt++)
                    #pragma unroll
                    for (int cp = 0; cp < 2; cp++) {
                        int col = cb * 128 + wc * 32 + nt * 8 + qc * 2 + cp;
                        if (col == grow)
                            g_diag[grow] = acc[mt][nt][rp * 2 + cp];
                    }
            }
            float s = 0.f;
            #pragma unroll
            for (int nt = 0; nt < 4; nt++)
                #pragma unroll
                for (int cp = 0; cp < 2; cp++)
                    s += ex2(fmaf(acc[mt][nt][rp * 2 + cp], L2E, noff));

            // quad butterfly: plain sum + max/argmax (no rescale needed)
            #pragma unroll
            for (int off = 1; off < 4; off <<= 1) {
                float m2 = __shfl_xor_sync(0xffffffffu, m, off);
                float s2 = __shfl_xor_sync(0xffffffffu, s, off);
                int   a2 = __shfl_xor_sync(0xffffffffu, ai, off);
                if (m2 > m || (m2 == m && a2 < ai)) ai = a2;
                m = fmaxf(m, m2);
                s += s2;
            }
            if (qc == 0) {
                smax[wc * 128 + lrow] = m;
                ssum[wc * 128 + lrow] = s;
                sarg[wc * 128 + lrow] = ai;
            }
        }
    }
    __syncthreads();

    // ---- merge 4 warp-cols; coalesced transposed write [cb][row] ----
    if (lane < 16) {
        const int lrow = wid * 16 + lane;
        const int grow = rb * 128 + lrow;
        float M = -FLT_MAX, S = 0.f;
        int AI = 0;
        #pragma unroll
        for (int w = 0; w < 4; w++) {
            float v = smax[w * 128 + lrow];
            if (v > M) { M = v; AI = sarg[w * 128 + lrow]; }  // ascending ties
            S += ssum[w * 128 + lrow];
        }
        int pi = cb * M_TOT + grow;
        g_pmax[pi] = M;
        g_psum[pi] = S;
        g_pami[pi] = AI;
    }
}

// ---------------------------------------------------------------------------
// Kernel 2: finalize. S is a plain sum of partials (shared offset SOFF);
// lse = SOFF + log(S). Argmax via max over partial maxima.
// ---------------------------------------------------------------------------
__global__ void __launch_bounds__(256) finalize_kernel(float* __restrict__ out) {
    __shared__ float s_loss[256];
    __shared__ int   s_corr[256];
    __shared__ int   s_last;
    const int tid = threadIdx.x;
    const int r = blockIdx.x * 256 + tid;

    float S = 0.f, bv = -FLT_MAX;
    int AI = 0;
    #pragma unroll
    for (int t = 0; t < NPART; t++) {
        float v = g_pmax[t * M_TOT + r];
        if (v > bv) { bv = v; AI = g_pami[t * M_TOT + r]; }  // first-idx ties
        S += g_psum[t * M_TOT + r];
    }
    float lse = SOFF + logf(S);

    s_loss[tid] = lse - g_diag[r];
    s_corr[tid] = (AI == r) ? 1 : 0;
    __syncthreads();
    for (int o = 128; o > 0; o >>= 1) {
        if (tid < o) {
            s_loss[tid] += s_loss[tid + o];
            s_corr[tid] += s_corr[tid + o];
        }
        __syncthreads();
    }
    if (tid == 0) {
        g_blk_loss[blockIdx.x] = s_loss[0];
        g_blk_corr[blockIdx.x] = s_corr[0];
        __threadfence();
        unsigned prev = atomicAdd(&g_done, 1u);
        s_last = (prev == NFBLK - 1) ? 1 : 0;
    }
    __syncthreads();

    if (s_last && tid == 0) {
        __threadfence();
        float L = 0.f;
        int Cc = 0;
        #pragma unroll
        for (int i = 0; i < NFBLK; i++) {   // fixed order -> deterministic
            L += g_blk_loss[i];
            Cc += g_blk_corr[i];
        }
        out[0] = L / (float)M_TOT;
        out[1] = 100.f * (float)Cc / (float)M_TOT;
        g_done = 0;                          // reset for graph replay
    }
}

// ---------------------------------------------------------------------------
extern "C" void kernel_launch(void* const* d_in, const int* in_sizes, int n_in,
                              void* d_out, int out_size) {
    const float* pred = (const float*)d_in[0];
    const float* gt   = (const float*)d_in[1];

    cudaFuncSetAttribute(gemm_softmax_kernel,
                         cudaFuncAttributeMaxDynamicSharedMemorySize, SM_TOTAL);

    pack_kernel<<<4 * NPAGE, 256>>>(pred, gt);
    gemm_softmax_kernel<<<1024, 256, SM_TOTAL>>>();
    finalize_kernel<<<NFBLK, 256>>>((float*)d_out);
}